// round 2
// baseline (speedup 1.0000x reference)
#include <cuda_runtime.h>

// Problem constants
#define IN_SZ   8192
#define OUT_SZ  8192
#define OUT4    (OUT_SZ / 4)            // 2048 float4 columns
// sigmoid(2.0)
#define SIG_TAU 0.8807970779778823f

// Main-kernel tiling
#define THREADS          256
#define COLS4_PER_BLOCK  256            // one float4 column per thread
#define GRID_X           (OUT4 / COLS4_PER_BLOCK)   // 8
#define NSLICE           128            // split-K row slices
#define ROWS_PER_SLICE   (IN_SZ / NSLICE)           // 64

// Deterministic split-K scratch (no atomics -> bitwise-reproducible spikes)
__device__ float g_partial[NSLICE * OUT_SZ];   // 4 MB

// Fused pass over the [IN_SZ, OUT_SZ] plane:
//   - J_out = SIG_TAU * J + x[i]          (elementwise, 512 MB of the 768 MB total)
//   - acc[j] += x[i] * W[i][j]            (split-K partial GEMV, 256 MB read)
// All big streams are touch-once: use .cs (evict-first) load/store hints.
__global__ __launch_bounds__(THREADS, 1)
void ostl_main_kernel(const float* __restrict__ x,
                      const float* __restrict__ J,
                      const float* __restrict__ W,
                      float* __restrict__ Jout)
{
    __shared__ float sx[ROWS_PER_SLICE];

    const int c    = blockIdx.x * COLS4_PER_BLOCK + threadIdx.x;  // float4 column
    const int row0 = blockIdx.y * ROWS_PER_SLICE;

    for (int i = threadIdx.x; i < ROWS_PER_SLICE; i += THREADS)
        sx[i] = x[row0 + i];
    __syncthreads();

    const float4* __restrict__ W4 = (const float4*)W;
    const float4* __restrict__ J4 = (const float4*)J;
    float4*       __restrict__ O4 = (float4*)Jout;

    float4 acc = make_float4(0.f, 0.f, 0.f, 0.f);
    int idx = row0 * OUT4 + c;   // max 16,777,215 -> fits int

    #pragma unroll 4
    for (int r = 0; r < ROWS_PER_SLICE; ++r, idx += OUT4) {
        const float xi = sx[r];
        const float4 w = __ldcs(&W4[idx]);   // streaming read (touch-once)
        const float4 j = __ldcs(&J4[idx]);   // streaming read (touch-once)

        acc.x = fmaf(xi, w.x, acc.x);
        acc.y = fmaf(xi, w.y, acc.y);
        acc.z = fmaf(xi, w.z, acc.z);
        acc.w = fmaf(xi, w.w, acc.w);

        float4 o;
        o.x = fmaf(SIG_TAU, j.x, xi);
        o.y = fmaf(SIG_TAU, j.y, xi);
        o.z = fmaf(SIG_TAU, j.z, xi);
        o.w = fmaf(SIG_TAU, j.w, xi);
        __stcs(&O4[idx], o);                 // streaming write
    }

    // Deterministic per-slice partial store (coalesced float4).
    // Keep in L2 (default policy) — the epilogue re-reads it immediately.
    ((float4*)g_partial)[blockIdx.y * OUT4 + c] = acc;
}

// Reduce split-K partials, apply LIF cell update, emit u_out and s.
// Spread across many SMs: 128 blocks x 64 threads (one thread per output j).
#define EPI_BLOCK 64
#define EPI_GRID  (OUT_SZ / EPI_BLOCK)   // 128
__global__ __launch_bounds__(EPI_BLOCK, 1)
void ostl_epilogue_kernel(const float* __restrict__ u,
                          float* __restrict__ out_u,
                          float* __restrict__ out_s)
{
    const int j = blockIdx.x * EPI_BLOCK + threadIdx.x;

    float I = 0.f;
    #pragma unroll 16
    for (int k = 0; k < NSLICE; ++k)
        I += g_partial[k * OUT_SZ + j];          // coalesced across threads, MLP=16

    const float u_new = fmaf(SIG_TAU, u[j], I);
    const float s     = (u_new - 1.0f) > 0.f ? 1.0f : 0.0f;  // V_TH = 1
    out_u[j] = u_new - s;                        // V_TH - V_RESET = 1
    out_s[j] = s;
}

extern "C" void kernel_launch(void* const* d_in, const int* in_sizes, int n_in,
                              void* d_out, int out_size)
{
    const float* x = (const float*)d_in[0];
    const float* u = (const float*)d_in[1];
    const float* J = (const float*)d_in[2];
    const float* W = (const float*)d_in[3];

    float* out   = (float*)d_out;
    float* out_u = out;                                   // [0, 8192)
    float* out_J = out + OUT_SZ;                          // [8192, 8192+64M)
    float* out_s = out + OUT_SZ + (size_t)IN_SZ * OUT_SZ; // last 8192

    dim3 grid(GRID_X, NSLICE);
    ostl_main_kernel<<<grid, THREADS>>>(x, J, W, out_J);
    ostl_epilogue_kernel<<<EPI_GRID, EPI_BLOCK>>>(u, out_u, out_s);
}

// round 3
// speedup vs baseline: 1.0665x; 1.0665x over previous
#include <cuda_runtime.h>

// Problem constants
#define IN_SZ   8192
#define OUT_SZ  8192
#define OUT4    (OUT_SZ / 4)            // 2048 float4 columns
// sigmoid(2.0)
#define SIG_TAU 0.8807970779778823f

// Main-kernel tiling
#define THREADS          256
#define COLS4_PER_BLOCK  256            // one float4 column per thread
#define GRID_X           (OUT4 / COLS4_PER_BLOCK)   // 8
#define NSLICE           128            // split-K row slices
#define ROWS_PER_SLICE   (IN_SZ / NSLICE)           // 64

// Deterministic split-K scratch (no atomics -> bitwise-reproducible spikes)
__device__ float g_partial[NSLICE * OUT_SZ];   // 4 MB

// Fused pass over the [IN_SZ, OUT_SZ] plane (plain loads — .cs hints measured slower):
//   - J_out = SIG_TAU * J + x[i]          (elementwise, 512 MB of the 768 MB total)
//   - acc[j] += x[i] * W[i][j]            (split-K partial GEMV, 256 MB read)
__global__ __launch_bounds__(THREADS, 1)
void ostl_main_kernel(const float* __restrict__ x,
                      const float* __restrict__ J,
                      const float* __restrict__ W,
                      float* __restrict__ Jout)
{
    __shared__ float sx[ROWS_PER_SLICE];

    const int c    = blockIdx.x * COLS4_PER_BLOCK + threadIdx.x;  // float4 column
    const int row0 = blockIdx.y * ROWS_PER_SLICE;

    for (int i = threadIdx.x; i < ROWS_PER_SLICE; i += THREADS)
        sx[i] = x[row0 + i];
    __syncthreads();

    const float4* __restrict__ W4 = (const float4*)W;
    const float4* __restrict__ J4 = (const float4*)J;
    float4*       __restrict__ O4 = (float4*)Jout;

    float4 acc = make_float4(0.f, 0.f, 0.f, 0.f);
    int idx = row0 * OUT4 + c;   // max 16,777,215 -> fits int

    #pragma unroll 4
    for (int r = 0; r < ROWS_PER_SLICE; ++r, idx += OUT4) {
        const float xi = sx[r];
        const float4 w = W4[idx];
        const float4 j = J4[idx];

        acc.x = fmaf(xi, w.x, acc.x);
        acc.y = fmaf(xi, w.y, acc.y);
        acc.z = fmaf(xi, w.z, acc.z);
        acc.w = fmaf(xi, w.w, acc.w);

        float4 o;
        o.x = fmaf(SIG_TAU, j.x, xi);
        o.y = fmaf(SIG_TAU, j.y, xi);
        o.z = fmaf(SIG_TAU, j.z, xi);
        o.w = fmaf(SIG_TAU, j.w, xi);
        O4[idx] = o;
    }

    // Deterministic per-slice partial store (coalesced float4, lands in L2)
    ((float4*)g_partial)[blockIdx.y * OUT4 + c] = acc;
}

// Epilogue: reduce the 128 x 8192 partials, apply LIF update, emit u_out and s.
// float4-vectorized; 4 threads cooperate per float4 column (32 slices each),
// combined in a fixed order via shared memory -> bitwise deterministic.
#define EPI_THREADS 256
#define EPI_COLS4   64                       // float4 columns per block
#define EPI_GRID    (OUT4 / EPI_COLS4)       // 32 blocks
__global__ __launch_bounds__(EPI_THREADS, 1)
void ostl_epilogue_kernel(const float* __restrict__ u,
                          float* __restrict__ out_u,
                          float* __restrict__ out_s)
{
    __shared__ float4 sacc[3][EPI_COLS4];

    const int lc = threadIdx.x & (EPI_COLS4 - 1);    // local float4 column
    const int q  = threadIdx.x >> 6;                 // slice quarter 0..3
    const int c  = blockIdx.x * EPI_COLS4 + lc;

    const float4* __restrict__ P4 = (const float4*)g_partial;

    float4 a = make_float4(0.f, 0.f, 0.f, 0.f);
    int idx = (q * 32) * OUT4 + c;
    #pragma unroll 8
    for (int k = 0; k < 32; ++k, idx += OUT4) {
        const float4 p = P4[idx];                    // warp-coalesced 512B lines
        a.x += p.x; a.y += p.y; a.z += p.z; a.w += p.w;
    }

    if (q > 0) sacc[q - 1][lc] = a;
    __syncthreads();

    if (q == 0) {
        #pragma unroll
        for (int t = 0; t < 3; ++t) {                // fixed combine order
            const float4 b = sacc[t][lc];
            a.x += b.x; a.y += b.y; a.z += b.z; a.w += b.w;
        }
        const float4 uu = ((const float4*)u)[c];
        float4 uo, so;
        {
            float un;
            un = fmaf(SIG_TAU, uu.x, a.x); so.x = (un - 1.0f) > 0.f ? 1.f : 0.f; uo.x = un - so.x;
            un = fmaf(SIG_TAU, uu.y, a.y); so.y = (un - 1.0f) > 0.f ? 1.f : 0.f; uo.y = un - so.y;
            un = fmaf(SIG_TAU, uu.z, a.z); so.z = (un - 1.0f) > 0.f ? 1.f : 0.f; uo.z = un - so.z;
            un = fmaf(SIG_TAU, uu.w, a.w); so.w = (un - 1.0f) > 0.f ? 1.f : 0.f; uo.w = un - so.w;
        }
        ((float4*)out_u)[c] = uo;
        ((float4*)out_s)[c] = so;
    }
}

extern "C" void kernel_launch(void* const* d_in, const int* in_sizes, int n_in,
                              void* d_out, int out_size)
{
    const float* x = (const float*)d_in[0];
    const float* u = (const float*)d_in[1];
    const float* J = (const float*)d_in[2];
    const float* W = (const float*)d_in[3];

    float* out   = (float*)d_out;
    float* out_u = out;                                   // [0, 8192)
    float* out_J = out + OUT_SZ;                          // [8192, 8192+64M)
    float* out_s = out + OUT_SZ + (size_t)IN_SZ * OUT_SZ; // last 8192

    dim3 grid(GRID_X, NSLICE);
    ostl_main_kernel<<<grid, THREADS>>>(x, J, W, out_J);
    ostl_epilogue_kernel<<<EPI_GRID, EPI_THREADS>>>(u, out_u, out_s);
}

// round 4
// speedup vs baseline: 1.0675x; 1.0010x over previous
#include <cuda_runtime.h>

// Problem constants
#define IN_SZ   8192
#define OUT_SZ  8192
#define OUT4    (OUT_SZ / 4)            // 2048 float4 columns
// sigmoid(2.0)
#define SIG_TAU 0.8807970779778823f

// Main-kernel tiling
#define THREADS          256
#define COLS4_PER_BLOCK  256            // one float4 column per thread
#define GRID_X           (OUT4 / COLS4_PER_BLOCK)   // 8
#define NSLICE           128            // split-K row slices
#define ROWS_PER_SLICE   (IN_SZ / NSLICE)           // 64

// Deterministic split-K scratch (no atomics -> bitwise-reproducible spikes)
__device__ float g_partial[NSLICE * OUT_SZ];   // 4 MB

// Fused pass over the [IN_SZ, OUT_SZ] plane (plain loads — .cs hints measured slower):
//   - J_out = SIG_TAU * J + x[i]          (elementwise, 512 MB of the 768 MB total)
//   - acc[j] += x[i] * W[i][j]            (split-K partial GEMV, 256 MB read)
__global__ __launch_bounds__(THREADS, 1)
void ostl_main_kernel(const float* __restrict__ x,
                      const float* __restrict__ J,
                      const float* __restrict__ W,
                      float* __restrict__ Jout)
{
    __shared__ float sx[ROWS_PER_SLICE];

    const int c    = blockIdx.x * COLS4_PER_BLOCK + threadIdx.x;  // float4 column
    const int row0 = blockIdx.y * ROWS_PER_SLICE;

    for (int i = threadIdx.x; i < ROWS_PER_SLICE; i += THREADS)
        sx[i] = x[row0 + i];
    __syncthreads();

    const float4* __restrict__ W4 = (const float4*)W;
    const float4* __restrict__ J4 = (const float4*)J;
    float4*       __restrict__ O4 = (float4*)Jout;

    float4 acc = make_float4(0.f, 0.f, 0.f, 0.f);
    int idx = row0 * OUT4 + c;   // max 16,777,215 -> fits int

    #pragma unroll 4
    for (int r = 0; r < ROWS_PER_SLICE; ++r, idx += OUT4) {
        const float xi = sx[r];
        const float4 w = W4[idx];
        const float4 j = J4[idx];

        acc.x = fmaf(xi, w.x, acc.x);
        acc.y = fmaf(xi, w.y, acc.y);
        acc.z = fmaf(xi, w.z, acc.z);
        acc.w = fmaf(xi, w.w, acc.w);

        float4 o;
        o.x = fmaf(SIG_TAU, j.x, xi);
        o.y = fmaf(SIG_TAU, j.y, xi);
        o.z = fmaf(SIG_TAU, j.z, xi);
        o.w = fmaf(SIG_TAU, j.w, xi);
        O4[idx] = o;
    }

    // Deterministic per-slice partial store (coalesced float4, lands in L2)
    ((float4*)g_partial)[blockIdx.y * OUT4 + c] = acc;
}

// Epilogue: reduce the 128 x 8192 partials, apply LIF update, emit u_out and s.
// 128 blocks x 256 threads: each block owns 16 float4 columns; 16 threads
// cooperate per column (8 slices each, fully unrolled), then combine in a
// fixed order through shared memory -> bitwise deterministic.
#define EPI_THREADS 256
#define EPI_COLS4   16                        // float4 columns per block
#define EPI_QGROUPS 16                        // threads per column
#define EPI_SLICES  (NSLICE / EPI_QGROUPS)    // 8 slices per thread
#define EPI_GRID    (OUT4 / EPI_COLS4)        // 128 blocks
__global__ __launch_bounds__(EPI_THREADS, 1)
void ostl_epilogue_kernel(const float* __restrict__ u,
                          float* __restrict__ out_u,
                          float* __restrict__ out_s)
{
    __shared__ float4 sacc[EPI_QGROUPS - 1][EPI_COLS4];

    const int lc = threadIdx.x & (EPI_COLS4 - 1);    // local float4 column 0..15
    const int q  = threadIdx.x >> 4;                 // slice group 0..15
    const int c  = blockIdx.x * EPI_COLS4 + lc;

    const float4* __restrict__ P4 = (const float4*)g_partial;

    float4 a = make_float4(0.f, 0.f, 0.f, 0.f);
    int idx = (q * EPI_SLICES) * OUT4 + c;
    #pragma unroll
    for (int k = 0; k < EPI_SLICES; ++k, idx += OUT4) {   // 8 independent loads
        const float4 p = P4[idx];
        a.x += p.x; a.y += p.y; a.z += p.z; a.w += p.w;
    }

    if (q > 0) sacc[q - 1][lc] = a;
    __syncthreads();

    if (q == 0) {
        #pragma unroll
        for (int t = 0; t < EPI_QGROUPS - 1; ++t) {       // fixed combine order
            const float4 b = sacc[t][lc];
            a.x += b.x; a.y += b.y; a.z += b.z; a.w += b.w;
        }
        const float4 uu = ((const float4*)u)[c];
        float4 uo, so;
        {
            float un;
            un = fmaf(SIG_TAU, uu.x, a.x); so.x = (un - 1.0f) > 0.f ? 1.f : 0.f; uo.x = un - so.x;
            un = fmaf(SIG_TAU, uu.y, a.y); so.y = (un - 1.0f) > 0.f ? 1.f : 0.f; uo.y = un - so.y;
            un = fmaf(SIG_TAU, uu.z, a.z); so.z = (un - 1.0f) > 0.f ? 1.f : 0.f; uo.z = un - so.z;
            un = fmaf(SIG_TAU, uu.w, a.w); so.w = (un - 1.0f) > 0.f ? 1.f : 0.f; uo.w = un - so.w;
        }
        ((float4*)out_u)[c] = uo;
        ((float4*)out_s)[c] = so;
    }
}

extern "C" void kernel_launch(void* const* d_in, const int* in_sizes, int n_in,
                              void* d_out, int out_size)
{
    const float* x = (const float*)d_in[0];
    const float* u = (const float*)d_in[1];
    const float* J = (const float*)d_in[2];
    const float* W = (const float*)d_in[3];

    float* out   = (float*)d_out;
    float* out_u = out;                                   // [0, 8192)
    float* out_J = out + OUT_SZ;                          // [8192, 8192+64M)
    float* out_s = out + OUT_SZ + (size_t)IN_SZ * OUT_SZ; // last 8192

    dim3 grid(GRID_X, NSLICE);
    ostl_main_kernel<<<grid, THREADS>>>(x, J, W, out_J);
    ostl_epilogue_kernel<<<EPI_GRID, EPI_THREADS>>>(u, out_u, out_s);
}